// round 16
// baseline (speedup 1.0000x reference)
#include <cuda_runtime.h>
#include <cuda_fp16.h>
#include <cstdint>

#define CCH 256
#define N0S 200000
#define N1S 50000
#define N2S 12500
#define E0S 800000
#define E1S 400000
#define LN_EPS 1e-5f

// ---------- device scratch ----------
__device__ __half g_xh[(size_t)N0S * CCH];
__device__ __half g_x1h[(size_t)N1S * CCH];
__device__ __half g_ah[(size_t)N1S * CCH];
__device__ float  g_H[(size_t)N1S * CCH];
__device__ __half g_wh[2 * CCH * 2 * CCH];
__device__ int g_deg0[N1S], g_cur0[N1S], g_off0[N1S + 1], g_srcs0[E0S];
__device__ int g_deg1[N2S], g_cur1[N2S], g_off1[N2S + 1], g_srcs1[E1S];
__device__ float g_sum[2][CCH], g_sumsq[2][CCH];

__device__ __forceinline__ uint32_t smem_to_u32(const void* p) {
    uint32_t a;
    asm("{ .reg .u64 t; cvta.to.shared.u64 t, %1; cvt.u32.u64 %0, t; }" : "=r"(a) : "l"(p));
    return a;
}
__device__ __forceinline__ void ldsm4(uint32_t* r, uint32_t addr) {
    asm volatile("ldmatrix.sync.aligned.m8n8.x4.shared.b16 {%0,%1,%2,%3}, [%4];"
        : "=r"(r[0]), "=r"(r[1]), "=r"(r[2]), "=r"(r[3]) : "r"(addr));
}
__device__ __forceinline__ void mma16816(float* c, const uint32_t* a, const uint32_t* b) {
    asm volatile("mma.sync.aligned.m16n8k16.row.col.f32.f16.f16.f32 "
        "{%0,%1,%2,%3}, {%4,%5,%6,%7}, {%8,%9}, {%0,%1,%2,%3};"
        : "+f"(c[0]), "+f"(c[1]), "+f"(c[2]), "+f"(c[3])
        : "r"(a[0]), "r"(a[1]), "r"(a[2]), "r"(a[3]), "r"(b[0]), "r"(b[1]));
}
__device__ __forceinline__ void cpa16(uint32_t d, const void* s) {
    asm volatile("cp.async.cg.shared.global [%0], [%1], 16;" :: "r"(d), "l"(s));
}
__device__ __forceinline__ void cpa16z(uint32_t d, const void* s, uint32_t sz) {
    asm volatile("cp.async.cg.shared.global [%0], [%1], 16, %2;" :: "r"(d), "l"(s), "r"(sz));
}
__device__ __forceinline__ void cpa_commit() { asm volatile("cp.async.commit_group;"); }
template <int N> __device__ __forceinline__ void cpa_wait() {
    asm volatile("cp.async.wait_group %0;" :: "n"(N));
}

// ---------- prep: fp32 -> fp16, MLP-8 (32 halfs per thread) ----------
__global__ void k_x2h(const float4* __restrict__ s, int n32) {
    int i = blockIdx.x * blockDim.x + threadIdx.x;
    if (i >= n32) return;
    float4 f[8];
    #pragma unroll
    for (int j = 0; j < 8; j++) f[j] = s[(size_t)i * 8 + j];
    uint4 o[4];
    __half2 h;
    #pragma unroll
    for (int j = 0; j < 4; j++) {
        h = __floats2half2_rn(f[j * 2].x, f[j * 2].y);     o[j].x = *(uint32_t*)&h;
        h = __floats2half2_rn(f[j * 2].z, f[j * 2].w);     o[j].y = *(uint32_t*)&h;
        h = __floats2half2_rn(f[j * 2 + 1].x, f[j * 2 + 1].y); o[j].z = *(uint32_t*)&h;
        h = __floats2half2_rn(f[j * 2 + 1].z, f[j * 2 + 1].w); o[j].w = *(uint32_t*)&h;
    }
    #pragma unroll
    for (int j = 0; j < 4; j++) ((uint4*)g_xh)[(size_t)i * 4 + j] = o[j];
}
__global__ void k_prepw(const float* __restrict__ Wl, const float* __restrict__ Wr, int woff) {
    int i = blockIdx.x * blockDim.x + threadIdx.x;
    if (i >= CCH * 2 * CCH) return;
    int o = i >> 9, k = i & 511;
    float v = (k < CCH) ? Wl[o * CCH + k] : Wr[o * CCH + k - CCH];
    g_wh[woff + i] = __float2half(v);
}

// ---------- CSR build ----------
__global__ void k_zero(int* deg, int* cur, int n, int layer) {
    int i = blockIdx.x * blockDim.x + threadIdx.x;
    if (i < n) { deg[i] = 0; cur[i] = 0; }
    if (i < CCH) { g_sum[layer][i] = 0.f; g_sumsq[layer][i] = 0.f; }
}
__global__ void k_hist(const int* __restrict__ dst, int* __restrict__ deg, int E) {
    int e = blockIdx.x * blockDim.x + threadIdx.x;
    if (e < E) atomicAdd(&deg[dst[e]], 1);
}
__global__ void k_scan(const int* __restrict__ deg, int* __restrict__ off, int n, int total) {
    __shared__ int part[1024];
    int t = threadIdx.x;
    int chunk = (n + 1023) >> 10;
    int b = min(t * chunk, n), e = min(b + chunk, n);
    int s = 0;
    for (int i = b; i < e; i++) s += deg[i];
    part[t] = s;
    __syncthreads();
    for (int d = 1; d < 1024; d <<= 1) {
        int v = (t >= d) ? part[t - d] : 0;
        __syncthreads();
        part[t] += v;
        __syncthreads();
    }
    int excl = t ? part[t - 1] : 0;
    for (int i = b; i < e; i++) { off[i] = excl; excl += deg[i]; }
    if (t == 0) off[n] = total;
}
__global__ void k_scatter(const int* __restrict__ src, const int* __restrict__ dst,
                          const int* __restrict__ off, int* __restrict__ cur,
                          int* __restrict__ srcs, int E) {
    int e = blockIdx.x * blockDim.x + threadIdx.x;
    if (e < E) {
        int d = dst[e];
        srcs[off[d] + atomicAdd(&cur[d], 1)] = src[e];
    }
}

// ---------- mean aggregate: warp/node, fp16 in -> fp16 out, MLP-4 ----------
__device__ __forceinline__ void add8(float* a, uint4 v) {
    __half2* h = (__half2*)&v;
    float2 f;
    f = __half22float2(h[0]); a[0] += f.x; a[1] += f.y;
    f = __half22float2(h[1]); a[2] += f.x; a[3] += f.y;
    f = __half22float2(h[2]); a[4] += f.x; a[5] += f.y;
    f = __half22float2(h[3]); a[6] += f.x; a[7] += f.y;
}
__global__ void k_aggr(const int* __restrict__ off, const int* __restrict__ srcs,
                       int layer, int n) {
    const uint4* __restrict__ X4 = (const uint4*)(layer ? g_x1h : g_xh);
    int wid = threadIdx.x >> 5, lane = threadIdx.x & 31;
    int b = blockIdx.x * 8 + wid;
    if (b >= n) return;
    int beg = off[b], end = off[b + 1];
    float acc[8] = {0, 0, 0, 0, 0, 0, 0, 0};
    int i = beg;
    for (; i + 4 <= end; i += 4) {
        int s0 = srcs[i], s1 = srcs[i + 1], s2 = srcs[i + 2], s3 = srcs[i + 3];
        uint4 v0 = X4[(size_t)s0 * 32 + lane];
        uint4 v1 = X4[(size_t)s1 * 32 + lane];
        uint4 v2 = X4[(size_t)s2 * 32 + lane];
        uint4 v3 = X4[(size_t)s3 * 32 + lane];
        add8(acc, v0); add8(acc, v1); add8(acc, v2); add8(acc, v3);
    }
    for (; i < end; i++) add8(acc, X4[(size_t)srcs[i] * 32 + lane]);
    int cnt = end - beg;
    float inv = 1.f / (float)(cnt > 0 ? cnt : 1);
    uint4 o;
    __half2 h;
    h = __floats2half2_rn(acc[0] * inv, acc[1] * inv); o.x = *(uint32_t*)&h;
    h = __floats2half2_rn(acc[2] * inv, acc[3] * inv); o.y = *(uint32_t*)&h;
    h = __floats2half2_rn(acc[4] * inv, acc[5] * inv); o.z = *(uint32_t*)&h;
    h = __floats2half2_rn(acc[6] * inv, acc[7] * inv); o.w = *(uint32_t*)&h;
    ((uint4*)g_ah)[(size_t)b * 32 + lane] = o;
}

// ---------- GEMM: fp16, K-chunk 128, 2-stage cp.async, fused stats (shfl-reduced) ----------
#define LDT 136
#define OF_A 0
#define OF_W 17408
#define STG_H 52224
#define SMEM_GEMM (2 * STG_H * 2)

__global__ __launch_bounds__(512) void k_gemm(const __half* __restrict__ ah,
                                              const __half* __restrict__ xt,
                                              const float* __restrict__ bias,
                                              int woff, int nrows, int layer) {
    extern __shared__ __half sm[];
    uint32_t sb = smem_to_u32(sm);
    int tid = threadIdx.x, lane = tid & 31, wid = tid >> 5;
    int row0 = blockIdx.x * 128;
    int wm = wid >> 2, wn = wid & 3;
    int r0w = wm * 32, n0w = wn * 64;

    float acc[2][8][4];
    #pragma unroll
    for (int a = 0; a < 2; a++)
        #pragma unroll
        for (int b = 0; b < 8; b++)
            #pragma unroll
            for (int c = 0; c < 4; c++) acc[a][b][c] = 0.f;

    uint32_t aoff = (uint32_t)((lane & 15) * LDT + (lane >> 4) * 8);
    uint32_t boff = (uint32_t)(((lane & 7) + (lane >> 4) * 8) * LDT + ((lane >> 3) & 1) * 8);

    auto prefetch = [&](int kc) {
        uint32_t base = sb + (uint32_t)((kc & 1) * STG_H) * 2;
        const __half* __restrict__ src = (kc < 2) ? ah : xt;
        int col0 = (kc & 1) * 128;
        #pragma unroll
        for (int it = 0; it < 4; it++) {
            int i = tid + it * 512;
            int r = i >> 4, c = (i & 15) * 8;
            int gr = row0 + r;
            uint32_t sz = (gr < nrows) ? 16u : 0u;
            cpa16z(base + (uint32_t)(OF_A + r * LDT + c) * 2, &src[(size_t)gr * CCH + col0 + c], sz);
        }
        #pragma unroll
        for (int it = 0; it < 8; it++) {
            int i = tid + it * 512;
            int r = i >> 4, c = (i & 15) * 8;
            cpa16(base + (uint32_t)(OF_W + r * LDT + c) * 2,
                  &g_wh[(size_t)woff + (size_t)r * 512 + kc * 128 + c]);
        }
        cpa_commit();
    };

    prefetch(0);
    for (int kc = 0; kc < 4; kc++) {
        if (kc < 3) { prefetch(kc + 1); cpa_wait<1>(); } else { cpa_wait<0>(); }
        __syncthreads();
        uint32_t base = sb + (uint32_t)((kc & 1) * STG_H) * 2;
        #pragma unroll
        for (int ks = 0; ks < 8; ks++) {
            uint32_t k0 = ks * 16;
            uint32_t af[2][4], bf[4][4];
            #pragma unroll
            for (int mt = 0; mt < 2; mt++)
                ldsm4(af[mt], base + (uint32_t)(OF_A + (r0w + mt * 16) * LDT + k0 + aoff) * 2);
            #pragma unroll
            for (int g = 0; g < 4; g++)
                ldsm4(bf[g], base + (uint32_t)(OF_W + (n0w + g * 16) * LDT + k0 + boff) * 2);
            #pragma unroll
            for (int mt = 0; mt < 2; mt++)
                #pragma unroll
                for (int nt = 0; nt < 8; nt++)
                    mma16816(acc[mt][nt], af[mt], &bf[nt >> 1][(nt & 1) * 2]);
        }
        __syncthreads();
    }
    float* s_s = (float*)sm;
    float* s_q = (float*)sm + 1024;

    int g = lane >> 2, t4 = lane & 3;
    #pragma unroll
    for (int nt = 0; nt < 8; nt++) {
        int col = n0w + nt * 8 + t4 * 2;
        float b0 = bias[col], b1 = bias[col + 1];
        float s0 = 0.f, s1 = 0.f, q0 = 0.f, q1 = 0.f;
        #pragma unroll
        for (int mt = 0; mt < 2; mt++) {
            int row = row0 + r0w + mt * 16 + g;
            if (row < nrows) {
                float y0 = fmaxf(acc[mt][nt][0] + b0, 0.f);
                float y1 = fmaxf(acc[mt][nt][1] + b1, 0.f);
                g_H[(size_t)row * CCH + col] = y0;
                g_H[(size_t)row * CCH + col + 1] = y1;
                s0 += y0; q0 += y0 * y0; s1 += y1; q1 += y1 * y1;
            }
            if (row + 8 < nrows) {
                float y2 = fmaxf(acc[mt][nt][2] + b0, 0.f);
                float y3 = fmaxf(acc[mt][nt][3] + b1, 0.f);
                g_H[(size_t)(row + 8) * CCH + col] = y2;
                g_H[(size_t)(row + 8) * CCH + col + 1] = y3;
                s0 += y2; q0 += y2 * y2; s1 += y3; q1 += y3 * y3;
            }
        }
        #pragma unroll
        for (int o = 4; o < 32; o <<= 1) {
            s0 += __shfl_xor_sync(0xffffffff, s0, o);
            s1 += __shfl_xor_sync(0xffffffff, s1, o);
            q0 += __shfl_xor_sync(0xffffffff, q0, o);
            q1 += __shfl_xor_sync(0xffffffff, q1, o);
        }
        if (g == 0) {
            s_s[wm * 256 + col] = s0; s_s[wm * 256 + col + 1] = s1;
            s_q[wm * 256 + col] = q0; s_q[wm * 256 + col + 1] = q1;
        }
    }
    __syncthreads();
    if (tid < 256) {
        float ts = s_s[tid] + s_s[256 + tid] + s_s[512 + tid] + s_s[768 + tid];
        float tq = s_q[tid] + s_q[256 + tid] + s_q[512 + tid] + s_q[768 + tid];
        atomicAdd(&g_sum[layer][tid], ts);
        atomicAdd(&g_sumsq[layer][tid], tq);
    }
}

// ---------- normalize (finstats inlined, per-thread from g_sum) ----------
__global__ void k_norm(const float* __restrict__ gamma, const float* __restrict__ beta,
                       float* __restrict__ out, int n, int layer, int mode) {
    int i4 = blockIdx.x * blockDim.x + threadIdx.x;
    if (i4 >= n * (CCH / 4)) return;
    int i = i4 * 4;
    int ch = i & (CCH - 1);
    float invn = 1.f / (float)n;
    float4 h = *(const float4*)&g_H[i];
    float4 y;
    #pragma unroll
    for (int c = 0; c < 4; c++) {
        float mu = g_sum[layer][ch + c] * invn;
        float var = g_sumsq[layer][ch + c] * invn - mu * mu;
        float sc = gamma[ch + c] * rsqrtf(var + LN_EPS);
        ((float*)&y)[c] = sc * ((float*)&h)[c] + beta[ch + c] - sc * mu;
    }
    if (mode == 0) {
        __half2 a = __floats2half2_rn(y.x, y.y), b = __floats2half2_rn(y.z, y.w);
        uint2 p = {*(uint32_t*)&a, *(uint32_t*)&b};
        *(uint2*)&g_x1h[i] = p;
    } else {
        *(float4*)&out[i] = y;
    }
}

// ---------- launcher ----------
extern "C" void kernel_launch(void* const* d_in, const int* in_sizes, int n_in,
                              void* d_out, int out_size) {
    const float* x = (const float*)d_in[0];
    const int* e0s = (const int*)d_in[1];
    const int* e0d = (const int*)d_in[2];
    const int* e1s = (const int*)d_in[3];
    const int* e1d = (const int*)d_in[4];
    const float* Wl0 = (const float*)d_in[5];
    const float* bl0 = (const float*)d_in[6];
    const float* Wr0 = (const float*)d_in[7];
    const float* g0  = (const float*)d_in[8];
    const float* be0 = (const float*)d_in[9];
    const float* Wl1 = (const float*)d_in[10];
    const float* bl1 = (const float*)d_in[11];
    const float* Wr1 = (const float*)d_in[12];
    const float* g1  = (const float*)d_in[13];
    const float* be1 = (const float*)d_in[14];
    float* out = (float*)d_out;
    const int E0 = in_sizes[1], E1 = in_sizes[3];

    static bool init = false;
    static cudaStream_t s1, s2, s3;
    static cudaEvent_t ef, e1, e2, e3;
    if (!init) {
        cudaFuncSetAttribute(k_gemm, cudaFuncAttributeMaxDynamicSharedMemorySize, SMEM_GEMM);
        cudaStreamCreateWithFlags(&s1, cudaStreamNonBlocking);
        cudaStreamCreateWithFlags(&s2, cudaStreamNonBlocking);
        cudaStreamCreateWithFlags(&s3, cudaStreamNonBlocking);
        cudaEventCreateWithFlags(&ef, cudaEventDisableTiming);
        cudaEventCreateWithFlags(&e1, cudaEventDisableTiming);
        cudaEventCreateWithFlags(&e2, cudaEventDisableTiming);
        cudaEventCreateWithFlags(&e3, cudaEventDisableTiming);
        init = true;
    }

    __half *d_ah, *d_xh, *d_x1h;
    int *d_deg0, *d_cur0, *d_off0, *d_srcs0, *d_deg1, *d_cur1, *d_off1, *d_srcs1;
    cudaGetSymbolAddress((void**)&d_ah, g_ah);
    cudaGetSymbolAddress((void**)&d_xh, g_xh);
    cudaGetSymbolAddress((void**)&d_x1h, g_x1h);
    cudaGetSymbolAddress((void**)&d_deg0, g_deg0);
    cudaGetSymbolAddress((void**)&d_cur0, g_cur0);
    cudaGetSymbolAddress((void**)&d_off0, g_off0);
    cudaGetSymbolAddress((void**)&d_srcs0, g_srcs0);
    cudaGetSymbolAddress((void**)&d_deg1, g_deg1);
    cudaGetSymbolAddress((void**)&d_cur1, g_cur1);
    cudaGetSymbolAddress((void**)&d_off1, g_off1);
    cudaGetSymbolAddress((void**)&d_srcs1, g_srcs1);

    // fork
    cudaEventRecord(ef, 0);
    cudaStreamWaitEvent(s1, ef, 0);
    cudaStreamWaitEvent(s2, ef, 0);
    cudaStreamWaitEvent(s3, ef, 0);

    // main: fp16 conversion of x (MLP-8)
    k_x2h<<<(N0S * CCH / 32 + 255) / 256, 256>>>((const float4*)x, N0S * CCH / 32);

    // s1: weights
    k_prepw<<<(CCH * 512 + 255) / 256, 256, 0, s1>>>(Wl0, Wr0, 0);
    k_prepw<<<(CCH * 512 + 255) / 256, 256, 0, s1>>>(Wl1, Wr1, CCH * 512);
    cudaEventRecord(e1, s1);

    // s2: CSR layer 0
    k_zero<<<(N1S + 255) / 256, 256, 0, s2>>>(d_deg0, d_cur0, N1S, 0);
    k_hist<<<(E0 + 255) / 256, 256, 0, s2>>>(e0d, d_deg0, E0);
    k_scan<<<1, 1024, 0, s2>>>(d_deg0, d_off0, N1S, E0);
    k_scatter<<<(E0 + 255) / 256, 256, 0, s2>>>(e0s, e0d, d_off0, d_cur0, d_srcs0, E0);
    cudaEventRecord(e2, s2);

    // s3: CSR layer 1
    k_zero<<<(N2S + 255) / 256, 256, 0, s3>>>(d_deg1, d_cur1, N2S, 1);
    k_hist<<<(E1 + 255) / 256, 256, 0, s3>>>(e1d, d_deg1, E1);
    k_scan<<<1, 1024, 0, s3>>>(d_deg1, d_off1, N2S, E1);
    k_scatter<<<(E1 + 255) / 256, 256, 0, s3>>>(e1s, e1d, d_off1, d_cur1, d_srcs1, E1);
    cudaEventRecord(e3, s3);

    // layer 0
    cudaStreamWaitEvent(0, e2, 0);
    k_aggr<<<(N1S + 7) / 8, 256>>>(d_off0, d_srcs0, 0, N1S);
    cudaStreamWaitEvent(0, e1, 0);
    k_gemm<<<(N1S + 127) / 128, 512, SMEM_GEMM>>>(d_ah, d_xh, bl0, 0, N1S, 0);
    k_norm<<<(N1S * 64 + 255) / 256, 256>>>(g0, be0, out, N1S, 0, 0);

    // layer 1
    cudaStreamWaitEvent(0, e3, 0);
    k_aggr<<<(N2S + 7) / 8, 256>>>(d_off1, d_srcs1, 1, N2S);
    k_gemm<<<(N2S + 127) / 128, 512, SMEM_GEMM>>>(d_ah, d_x1h, bl1, CCH * 512, N2S, 1);
    k_norm<<<(N2S * 64 + 255) / 256, 256>>>(g1, be1, out, N2S, 1, 1);
}

// round 17
// speedup vs baseline: 1.0330x; 1.0330x over previous
#include <cuda_runtime.h>
#include <cuda_fp16.h>
#include <cstdint>

#define CCH 256
#define N0S 200000
#define N1S 50000
#define N2S 12500
#define E0S 800000
#define E1S 400000
#define LN_EPS 1e-5f

// ---------- device scratch ----------
__device__ __half g_xh[(size_t)N0S * CCH];
__device__ __half g_x1h[(size_t)N1S * CCH];
__device__ __half g_ah[(size_t)N1S * CCH];
__device__ float  g_H[(size_t)N1S * CCH];
__device__ __half g_wh[2 * CCH * 2 * CCH];
__device__ int g_deg0[N1S], g_cur0[N1S], g_off0[N1S + 1], g_srcs0[E0S];
__device__ int g_deg1[N2S], g_cur1[N2S], g_off1[N2S + 1], g_srcs1[E1S];
__device__ float g_sum[2][CCH], g_sumsq[2][CCH];

__device__ __forceinline__ uint32_t smem_to_u32(const void* p) {
    uint32_t a;
    asm("{ .reg .u64 t; cvta.to.shared.u64 t, %1; cvt.u32.u64 %0, t; }" : "=r"(a) : "l"(p));
    return a;
}
__device__ __forceinline__ void ldsm4(uint32_t* r, uint32_t addr) {
    asm volatile("ldmatrix.sync.aligned.m8n8.x4.shared.b16 {%0,%1,%2,%3}, [%4];"
        : "=r"(r[0]), "=r"(r[1]), "=r"(r[2]), "=r"(r[3]) : "r"(addr));
}
__device__ __forceinline__ void mma16816(float* c, const uint32_t* a, const uint32_t* b) {
    asm volatile("mma.sync.aligned.m16n8k16.row.col.f32.f16.f16.f32 "
        "{%0,%1,%2,%3}, {%4,%5,%6,%7}, {%8,%9}, {%0,%1,%2,%3};"
        : "+f"(c[0]), "+f"(c[1]), "+f"(c[2]), "+f"(c[3])
        : "r"(a[0]), "r"(a[1]), "r"(a[2]), "r"(a[3]), "r"(b[0]), "r"(b[1]));
}
__device__ __forceinline__ void cpa16(uint32_t d, const void* s) {
    asm volatile("cp.async.cg.shared.global [%0], [%1], 16;" :: "r"(d), "l"(s));
}
__device__ __forceinline__ void cpa16z(uint32_t d, const void* s, uint32_t sz) {
    asm volatile("cp.async.cg.shared.global [%0], [%1], 16, %2;" :: "r"(d), "l"(s), "r"(sz));
}
__device__ __forceinline__ void cpa_commit() { asm volatile("cp.async.commit_group;"); }
template <int N> __device__ __forceinline__ void cpa_wait() {
    asm volatile("cp.async.wait_group %0;" :: "n"(N));
}

// ---------- prep: fp32 -> fp16, MLP-4 ----------
__global__ void k_x2h(const float4* __restrict__ s, int n16) {
    int i = blockIdx.x * blockDim.x + threadIdx.x;
    if (i >= n16) return;
    float4 a = s[i * 4], b = s[i * 4 + 1], c = s[i * 4 + 2], d = s[i * 4 + 3];
    uint4 o0, o1;
    __half2 h;
    h = __floats2half2_rn(a.x, a.y); o0.x = *(uint32_t*)&h;
    h = __floats2half2_rn(a.z, a.w); o0.y = *(uint32_t*)&h;
    h = __floats2half2_rn(b.x, b.y); o0.z = *(uint32_t*)&h;
    h = __floats2half2_rn(b.z, b.w); o0.w = *(uint32_t*)&h;
    h = __floats2half2_rn(c.x, c.y); o1.x = *(uint32_t*)&h;
    h = __floats2half2_rn(c.z, c.w); o1.y = *(uint32_t*)&h;
    h = __floats2half2_rn(d.x, d.y); o1.z = *(uint32_t*)&h;
    h = __floats2half2_rn(d.z, d.w); o1.w = *(uint32_t*)&h;
    ((uint4*)g_xh)[i * 2] = o0;
    ((uint4*)g_xh)[i * 2 + 1] = o1;
}
__global__ void k_prepw(const float* __restrict__ Wl, const float* __restrict__ Wr, int woff) {
    int i = blockIdx.x * blockDim.x + threadIdx.x;
    if (i >= CCH * 2 * CCH) return;
    int o = i >> 9, k = i & 511;
    float v = (k < CCH) ? Wl[o * CCH + k] : Wr[o * CCH + k - CCH];
    g_wh[woff + i] = __float2half(v);
}

// ---------- CSR build (both layers' zero merged) ----------
__global__ void k_zeroall() {
    int i = blockIdx.x * blockDim.x + threadIdx.x;
    if (i < N1S) { g_deg0[i] = 0; g_cur0[i] = 0; }
    if (i < N2S) { g_deg1[i] = 0; g_cur1[i] = 0; }
    if (i < CCH) {
        g_sum[0][i] = 0.f; g_sumsq[0][i] = 0.f;
        g_sum[1][i] = 0.f; g_sumsq[1][i] = 0.f;
    }
}
__global__ void k_hist(const int* __restrict__ dst, int* __restrict__ deg, int E) {
    int e = blockIdx.x * blockDim.x + threadIdx.x;
    if (e < E) atomicAdd(&deg[dst[e]], 1);
}
__global__ void k_scan(const int* __restrict__ deg, int* __restrict__ off, int n, int total) {
    __shared__ int part[1024];
    int t = threadIdx.x;
    int chunk = (n + 1023) >> 10;
    int b = min(t * chunk, n), e = min(b + chunk, n);
    int s = 0;
    for (int i = b; i < e; i++) s += deg[i];
    part[t] = s;
    __syncthreads();
    for (int d = 1; d < 1024; d <<= 1) {
        int v = (t >= d) ? part[t - d] : 0;
        __syncthreads();
        part[t] += v;
        __syncthreads();
    }
    int excl = t ? part[t - 1] : 0;
    for (int i = b; i < e; i++) { off[i] = excl; excl += deg[i]; }
    if (t == 0) off[n] = total;
}
__global__ void k_scatter(const int* __restrict__ src, const int* __restrict__ dst,
                          const int* __restrict__ off, int* __restrict__ cur,
                          int* __restrict__ srcs, int E) {
    int e = blockIdx.x * blockDim.x + threadIdx.x;
    if (e < E) {
        int d = dst[e];
        srcs[off[d] + atomicAdd(&cur[d], 1)] = src[e];
    }
}

// ---------- mean aggregate: warp/node, fp16 in -> fp16 out, MLP-4 ----------
__device__ __forceinline__ void add8(float* a, uint4 v) {
    __half2* h = (__half2*)&v;
    float2 f;
    f = __half22float2(h[0]); a[0] += f.x; a[1] += f.y;
    f = __half22float2(h[1]); a[2] += f.x; a[3] += f.y;
    f = __half22float2(h[2]); a[4] += f.x; a[5] += f.y;
    f = __half22float2(h[3]); a[6] += f.x; a[7] += f.y;
}
__global__ void k_aggr(const int* __restrict__ off, const int* __restrict__ srcs,
                       int layer, int n) {
    const uint4* __restrict__ X4 = (const uint4*)(layer ? g_x1h : g_xh);
    int wid = threadIdx.x >> 5, lane = threadIdx.x & 31;
    int b = blockIdx.x * 16 + wid;
    if (b >= n) return;
    int beg = off[b], end = off[b + 1];
    float acc[8] = {0, 0, 0, 0, 0, 0, 0, 0};
    int i = beg;
    for (; i + 4 <= end; i += 4) {
        int s0 = srcs[i], s1 = srcs[i + 1], s2 = srcs[i + 2], s3 = srcs[i + 3];
        uint4 v0 = X4[(size_t)s0 * 32 + lane];
        uint4 v1 = X4[(size_t)s1 * 32 + lane];
        uint4 v2 = X4[(size_t)s2 * 32 + lane];
        uint4 v3 = X4[(size_t)s3 * 32 + lane];
        add8(acc, v0); add8(acc, v1); add8(acc, v2); add8(acc, v3);
    }
    for (; i < end; i++) add8(acc, X4[(size_t)srcs[i] * 32 + lane]);
    int cnt = end - beg;
    float inv = 1.f / (float)(cnt > 0 ? cnt : 1);
    uint4 o;
    __half2 h;
    h = __floats2half2_rn(acc[0] * inv, acc[1] * inv); o.x = *(uint32_t*)&h;
    h = __floats2half2_rn(acc[2] * inv, acc[3] * inv); o.y = *(uint32_t*)&h;
    h = __floats2half2_rn(acc[4] * inv, acc[5] * inv); o.z = *(uint32_t*)&h;
    h = __floats2half2_rn(acc[6] * inv, acc[7] * inv); o.w = *(uint32_t*)&h;
    ((uint4*)g_ah)[(size_t)b * 32 + lane] = o;
}

// ---------- GEMM: fp16, K-chunk 128, 2-stage cp.async, fused stats (shfl-reduced) ----------
#define LDT 136
#define OF_A 0
#define OF_W 17408
#define STG_H 52224
#define SMEM_GEMM (2 * STG_H * 2)

__global__ __launch_bounds__(512) void k_gemm(const __half* __restrict__ ah,
                                              const __half* __restrict__ xt,
                                              const float* __restrict__ bias,
                                              int woff, int nrows, int layer) {
    extern __shared__ __half sm[];
    uint32_t sb = smem_to_u32(sm);
    int tid = threadIdx.x, lane = tid & 31, wid = tid >> 5;
    int row0 = blockIdx.x * 128;
    int wm = wid >> 2, wn = wid & 3;
    int r0w = wm * 32, n0w = wn * 64;

    float acc[2][8][4];
    #pragma unroll
    for (int a = 0; a < 2; a++)
        #pragma unroll
        for (int b = 0; b < 8; b++)
            #pragma unroll
            for (int c = 0; c < 4; c++) acc[a][b][c] = 0.f;

    uint32_t aoff = (uint32_t)((lane & 15) * LDT + (lane >> 4) * 8);
    uint32_t boff = (uint32_t)(((lane & 7) + (lane >> 4) * 8) * LDT + ((lane >> 3) & 1) * 8);

    auto prefetch = [&](int kc) {
        uint32_t base = sb + (uint32_t)((kc & 1) * STG_H) * 2;
        const __half* __restrict__ src = (kc < 2) ? ah : xt;
        int col0 = (kc & 1) * 128;
        #pragma unroll
        for (int it = 0; it < 4; it++) {
            int i = tid + it * 512;
            int r = i >> 4, c = (i & 15) * 8;
            int gr = row0 + r;
            uint32_t sz = (gr < nrows) ? 16u : 0u;
            cpa16z(base + (uint32_t)(OF_A + r * LDT + c) * 2, &src[(size_t)gr * CCH + col0 + c], sz);
        }
        #pragma unroll
        for (int it = 0; it < 8; it++) {
            int i = tid + it * 512;
            int r = i >> 4, c = (i & 15) * 8;
            cpa16(base + (uint32_t)(OF_W + r * LDT + c) * 2,
                  &g_wh[(size_t)woff + (size_t)r * 512 + kc * 128 + c]);
        }
        cpa_commit();
    };

    prefetch(0);
    for (int kc = 0; kc < 4; kc++) {
        if (kc < 3) { prefetch(kc + 1); cpa_wait<1>(); } else { cpa_wait<0>(); }
        __syncthreads();
        uint32_t base = sb + (uint32_t)((kc & 1) * STG_H) * 2;
        #pragma unroll
        for (int ks = 0; ks < 8; ks++) {
            uint32_t k0 = ks * 16;
            uint32_t af[2][4], bf[4][4];
            #pragma unroll
            for (int mt = 0; mt < 2; mt++)
                ldsm4(af[mt], base + (uint32_t)(OF_A + (r0w + mt * 16) * LDT + k0 + aoff) * 2);
            #pragma unroll
            for (int g = 0; g < 4; g++)
                ldsm4(bf[g], base + (uint32_t)(OF_W + (n0w + g * 16) * LDT + k0 + boff) * 2);
            #pragma unroll
            for (int mt = 0; mt < 2; mt++)
                #pragma unroll
                for (int nt = 0; nt < 8; nt++)
                    mma16816(acc[mt][nt], af[mt], &bf[nt >> 1][(nt & 1) * 2]);
        }
        __syncthreads();
    }
    float* s_s = (float*)sm;
    float* s_q = (float*)sm + 1024;

    int g = lane >> 2, t4 = lane & 3;
    #pragma unroll
    for (int nt = 0; nt < 8; nt++) {
        int col = n0w + nt * 8 + t4 * 2;
        float b0 = bias[col], b1 = bias[col + 1];
        float s0 = 0.f, s1 = 0.f, q0 = 0.f, q1 = 0.f;
        #pragma unroll
        for (int mt = 0; mt < 2; mt++) {
            int row = row0 + r0w + mt * 16 + g;
            if (row < nrows) {
                float y0 = fmaxf(acc[mt][nt][0] + b0, 0.f);
                float y1 = fmaxf(acc[mt][nt][1] + b1, 0.f);
                g_H[(size_t)row * CCH + col] = y0;
                g_H[(size_t)row * CCH + col + 1] = y1;
                s0 += y0; q0 += y0 * y0; s1 += y1; q1 += y1 * y1;
            }
            if (row + 8 < nrows) {
                float y2 = fmaxf(acc[mt][nt][2] + b0, 0.f);
                float y3 = fmaxf(acc[mt][nt][3] + b1, 0.f);
                g_H[(size_t)(row + 8) * CCH + col] = y2;
                g_H[(size_t)(row + 8) * CCH + col + 1] = y3;
                s0 += y2; q0 += y2 * y2; s1 += y3; q1 += y3 * y3;
            }
        }
        #pragma unroll
        for (int o = 4; o < 32; o <<= 1) {
            s0 += __shfl_xor_sync(0xffffffff, s0, o);
            s1 += __shfl_xor_sync(0xffffffff, s1, o);
            q0 += __shfl_xor_sync(0xffffffff, q0, o);
            q1 += __shfl_xor_sync(0xffffffff, q1, o);
        }
        if (g == 0) {
            s_s[wm * 256 + col] = s0; s_s[wm * 256 + col + 1] = s1;
            s_q[wm * 256 + col] = q0; s_q[wm * 256 + col + 1] = q1;
        }
    }
    __syncthreads();
    if (tid < 256) {
        float ts = s_s[tid] + s_s[256 + tid] + s_s[512 + tid] + s_s[768 + tid];
        float tq = s_q[tid] + s_q[256 + tid] + s_q[512 + tid] + s_q[768 + tid];
        atomicAdd(&g_sum[layer][tid], ts);
        atomicAdd(&g_sumsq[layer][tid], tq);
    }
}

// ---------- normalize (finstats inlined, per-thread from g_sum) ----------
__global__ void k_norm(const float* __restrict__ gamma, const float* __restrict__ beta,
                       float* __restrict__ out, int n, int layer, int mode) {
    int i4 = blockIdx.x * blockDim.x + threadIdx.x;
    if (i4 >= n * (CCH / 4)) return;
    int i = i4 * 4;
    int ch = i & (CCH - 1);
    float invn = 1.f / (float)n;
    float4 h = *(const float4*)&g_H[i];
    float4 y;
    #pragma unroll
    for (int c = 0; c < 4; c++) {
        float mu = g_sum[layer][ch + c] * invn;
        float var = g_sumsq[layer][ch + c] * invn - mu * mu;
        float sc = gamma[ch + c] * rsqrtf(var + LN_EPS);
        ((float*)&y)[c] = sc * ((float*)&h)[c] + beta[ch + c] - sc * mu;
    }
    if (mode == 0) {
        __half2 a = __floats2half2_rn(y.x, y.y), b = __floats2half2_rn(y.z, y.w);
        uint2 p = {*(uint32_t*)&a, *(uint32_t*)&b};
        *(uint2*)&g_x1h[i] = p;
    } else {
        *(float4*)&out[i] = y;
    }
}

// ---------- launcher ----------
extern "C" void kernel_launch(void* const* d_in, const int* in_sizes, int n_in,
                              void* d_out, int out_size) {
    const float* x = (const float*)d_in[0];
    const int* e0s = (const int*)d_in[1];
    const int* e0d = (const int*)d_in[2];
    const int* e1s = (const int*)d_in[3];
    const int* e1d = (const int*)d_in[4];
    const float* Wl0 = (const float*)d_in[5];
    const float* bl0 = (const float*)d_in[6];
    const float* Wr0 = (const float*)d_in[7];
    const float* g0  = (const float*)d_in[8];
    const float* be0 = (const float*)d_in[9];
    const float* Wl1 = (const float*)d_in[10];
    const float* bl1 = (const float*)d_in[11];
    const float* Wr1 = (const float*)d_in[12];
    const float* g1  = (const float*)d_in[13];
    const float* be1 = (const float*)d_in[14];
    float* out = (float*)d_out;
    const int E0 = in_sizes[1], E1 = in_sizes[3];

    static bool init = false;
    static cudaStream_t s1, s2, s3;
    static cudaEvent_t ef, e1, e2, e2z, e3;
    if (!init) {
        cudaFuncSetAttribute(k_gemm, cudaFuncAttributeMaxDynamicSharedMemorySize, SMEM_GEMM);
        cudaStreamCreateWithFlags(&s1, cudaStreamNonBlocking);
        cudaStreamCreateWithFlags(&s2, cudaStreamNonBlocking);
        cudaStreamCreateWithFlags(&s3, cudaStreamNonBlocking);
        cudaEventCreateWithFlags(&ef, cudaEventDisableTiming);
        cudaEventCreateWithFlags(&e1, cudaEventDisableTiming);
        cudaEventCreateWithFlags(&e2, cudaEventDisableTiming);
        cudaEventCreateWithFlags(&e2z, cudaEventDisableTiming);
        cudaEventCreateWithFlags(&e3, cudaEventDisableTiming);
        init = true;
    }

    __half *d_ah, *d_xh, *d_x1h;
    int *d_cur0, *d_deg0, *d_off0, *d_srcs0, *d_deg1, *d_cur1, *d_off1, *d_srcs1;
    cudaGetSymbolAddress((void**)&d_ah, g_ah);
    cudaGetSymbolAddress((void**)&d_xh, g_xh);
    cudaGetSymbolAddress((void**)&d_x1h, g_x1h);
    cudaGetSymbolAddress((void**)&d_deg0, g_deg0);
    cudaGetSymbolAddress((void**)&d_cur0, g_cur0);
    cudaGetSymbolAddress((void**)&d_off0, g_off0);
    cudaGetSymbolAddress((void**)&d_srcs0, g_srcs0);
    cudaGetSymbolAddress((void**)&d_deg1, g_deg1);
    cudaGetSymbolAddress((void**)&d_cur1, g_cur1);
    cudaGetSymbolAddress((void**)&d_off1, g_off1);
    cudaGetSymbolAddress((void**)&d_srcs1, g_srcs1);

    // fork
    cudaEventRecord(ef, 0);
    cudaStreamWaitEvent(s1, ef, 0);
    cudaStreamWaitEvent(s2, ef, 0);
    cudaStreamWaitEvent(s3, ef, 0);

    // main: fp16 conversion of x (MLP-4)
    k_x2h<<<(N0S * CCH / 16 + 255) / 256, 256>>>((const float4*)x, N0S * CCH / 16);

    // s1: weights
    k_prepw<<<(CCH * 512 + 255) / 256, 256, 0, s1>>>(Wl0, Wr0, 0);
    k_prepw<<<(CCH * 512 + 255) / 256, 256, 0, s1>>>(Wl1, Wr1, CCH * 512);
    cudaEventRecord(e1, s1);

    // s2: zero both layers, then CSR layer 0
    k_zeroall<<<(N1S + 255) / 256, 256, 0, s2>>>();
    cudaEventRecord(e2z, s2);
    k_hist<<<(E0 + 255) / 256, 256, 0, s2>>>(e0d, d_deg0, E0);
    k_scan<<<1, 1024, 0, s2>>>(d_deg0, d_off0, N1S, E0);
    k_scatter<<<(E0 + 255) / 256, 256, 0, s2>>>(e0s, e0d, d_off0, d_cur0, d_srcs0, E0);
    cudaEventRecord(e2, s2);

    // s3: CSR layer 1 (waits for shared zeroing)
    cudaStreamWaitEvent(s3, e2z, 0);
    k_hist<<<(E1 + 255) / 256, 256, 0, s3>>>(e1d, d_deg1, E1);
    k_scan<<<1, 1024, 0, s3>>>(d_deg1, d_off1, N2S, E1);
    k_scatter<<<(E1 + 255) / 256, 256, 0, s3>>>(e1s, e1d, d_off1, d_cur1, d_srcs1, E1);
    cudaEventRecord(e3, s3);

    // layer 0
    cudaStreamWaitEvent(0, e2, 0);
    k_aggr<<<(N1S + 15) / 16, 512>>>(d_off0, d_srcs0, 0, N1S);
    cudaStreamWaitEvent(0, e1, 0);
    k_gemm<<<(N1S + 127) / 128, 512, SMEM_GEMM>>>(d_ah, d_xh, bl0, 0, N1S, 0);
    k_norm<<<(N1S * 64 + 255) / 256, 256>>>(g0, be0, out, N1S, 0, 0);

    // layer 1
    cudaStreamWaitEvent(0, e3, 0);
    k_aggr<<<(N2S + 15) / 16, 512>>>(d_off1, d_srcs1, 1, N2S);
    k_gemm<<<(N2S + 127) / 128, 512, SMEM_GEMM>>>(d_ah, d_x1h, bl1, CCH * 512, N2S, 1);
    k_norm<<<(N2S * 64 + 255) / 256, 256>>>(g1, be1, out, N2S, 1, 1);
}